// round 1
// baseline (speedup 1.0000x reference)
#include <cuda_runtime.h>
#include <math.h>

#define HIDDEN 1024
#define HEADS  8
#define HEAD   128
#define BATCH  512

// Scratch for gate pre-activations (allocation-free rule: __device__ globals)
__device__ float g_ig[BATCH * HEADS];
__device__ float g_fg[BATCH * HEADS];

// ---------------------------------------------------------------------------
// Kernel 1: gate pre-activations.  C[512,16] = concat(q,k,v) @ [Wi|Wf]^T + b
// One block per batch row; 256 threads; float4 loads; weights hit L2.
// ---------------------------------------------------------------------------
__global__ __launch_bounds__(256) void gates_kernel(
    const float* __restrict__ q, const float* __restrict__ k,
    const float* __restrict__ v,
    const float* __restrict__ Wi, const float* __restrict__ bi,
    const float* __restrict__ Wf, const float* __restrict__ bf)
{
    int b   = blockIdx.x;
    int tid = threadIdx.x;

    float acc_i[8] = {0,0,0,0,0,0,0,0};
    float acc_f[8] = {0,0,0,0,0,0,0,0};

    const float4* q4  = (const float4*)(q + (size_t)b * HIDDEN);
    const float4* k4  = (const float4*)(k + (size_t)b * HIDDEN);
    const float4* v4  = (const float4*)(v + (size_t)b * HIDDEN);
    const float4* Wi4 = (const float4*)Wi;   // [8][768] float4
    const float4* Wf4 = (const float4*)Wf;

    #pragma unroll
    for (int it = 0; it < 3; ++it) {
        int e4 = tid + it * 256;                       // 0..767
        float4 x = (it == 0) ? q4[tid] : (it == 1) ? k4[tid] : v4[tid];
        #pragma unroll
        for (int h = 0; h < 8; ++h) {
            float4 wi = Wi4[h * 768 + e4];
            acc_i[h] += x.x*wi.x + x.y*wi.y + x.z*wi.z + x.w*wi.w;
            float4 wf = Wf4[h * 768 + e4];
            acc_f[h] += x.x*wf.x + x.y*wf.y + x.z*wf.z + x.w*wf.w;
        }
    }

    // warp reduce all 16 accumulators
    #pragma unroll
    for (int h = 0; h < 8; ++h) {
        #pragma unroll
        for (int off = 16; off > 0; off >>= 1) {
            acc_i[h] += __shfl_down_sync(0xffffffffu, acc_i[h], off);
            acc_f[h] += __shfl_down_sync(0xffffffffu, acc_f[h], off);
        }
    }

    __shared__ float sred[8][16];
    int warp = tid >> 5, lane = tid & 31;
    if (lane == 0) {
        #pragma unroll
        for (int h = 0; h < 8; ++h) {
            sred[warp][h]     = acc_i[h];
            sred[warp][8 + h] = acc_f[h];
        }
    }
    __syncthreads();
    if (tid < 16) {
        float s = 0.f;
        #pragma unroll
        for (int w = 0; w < 8; ++w) s += sred[w][tid];
        if (tid < 8) g_ig[b * 8 + tid]     = s + bi[tid];
        else         g_fg[b * 8 + tid - 8] = s + bf[tid - 8];
    }
}

// ---------------------------------------------------------------------------
// Kernel 2: fully fused mLSTM step + GroupNorm.
// One block per (b,h).  256 threads stream the 128x128 cell tile once:
//   cell_new = f*cell + i * k_r * v_c   (written out)
//   num[c]  += q_r * cell_new[r,c]      (register accumulation, smem reduce)
// Then norm update, denominator, GroupNorm epilogue.
// ---------------------------------------------------------------------------
__global__ __launch_bounds__(256) void mlstm_kernel(
    const float* __restrict__ q, const float* __restrict__ k,
    const float* __restrict__ v, const float* __restrict__ cell,
    const float* __restrict__ norm, const float* __restrict__ maxs,
    const float* __restrict__ gamma, const float* __restrict__ beta,
    float* __restrict__ out, float* __restrict__ cell_out,
    float* __restrict__ norm_out, float* __restrict__ max_out)
{
    int bh  = blockIdx.x;
    int b   = bh >> 3;
    int h   = bh & 7;
    int tid = threadIdx.x;

    __shared__ __align__(16) float q_s[HEAD];
    __shared__ __align__(16) float k_s[HEAD];
    __shared__ __align__(16) float v_s[HEAD];
    __shared__ float4 snum[256];
    __shared__ float  red[HEAD];
    __shared__ float  red2[HEAD];
    __shared__ float  s_denom, s_mu, s_rstd;

    const float rsqrtD = 0.08838834764831845f;  // 1/sqrt(128)
    if (tid < HEAD) {
        q_s[tid] = q[(size_t)b * HIDDEN + h * HEAD + tid];
        k_s[tid] = k[(size_t)b * HIDDEN + h * HEAD + tid] * rsqrtD;
        v_s[tid] = v[(size_t)b * HIDDEN + h * HEAD + tid];
    }

    // gate scalars (uniform per block)
    float igp   = g_ig[bh];
    float fgp   = g_fg[bh];
    float log_f = fminf(fgp, 0.f) - log1pf(expf(-fabsf(fgp)));   // log sigmoid
    float m_old = maxs[bh];
    float m_new = fmaxf(igp, m_old + log_f);
    float i_g   = expf(igp - m_new);
    float f_g   = expf(log_f + m_old - m_new);
    __syncthreads();

    // cell tile: thread (r0 = tid/32, c4 = tid%32) -> columns 4*c4..4*c4+3
    int c4 = tid & 31;
    int r0 = tid >> 5;
    const float4* cell4 = (const float4*)(cell + (size_t)bh * HEAD * HEAD);
    float4* cout4 = cell_out ? (float4*)(cell_out + (size_t)bh * HEAD * HEAD) : (float4*)0;

    float4 vreg = ((const float4*)v_s)[c4];
    float4 num  = make_float4(0.f, 0.f, 0.f, 0.f);

    #pragma unroll 4
    for (int s = 0; s < 16; ++s) {
        int r = s * 8 + r0;
        float4 cv = cell4[r * 32 + c4];
        float  a  = i_g * k_s[r];
        float4 cn;
        cn.x = fmaf(f_g, cv.x, a * vreg.x);
        cn.y = fmaf(f_g, cv.y, a * vreg.y);
        cn.z = fmaf(f_g, cv.z, a * vreg.z);
        cn.w = fmaf(f_g, cv.w, a * vreg.w);
        if (cout4) cout4[r * 32 + c4] = cn;
        float qr = q_s[r];
        num.x = fmaf(qr, cn.x, num.x);
        num.y = fmaf(qr, cn.y, num.y);
        num.z = fmaf(qr, cn.z, num.z);
        num.w = fmaf(qr, cn.w, num.w);
    }

    // reduce num over the 8 row-groups (same c4 every 32 threads)
    snum[tid] = num;
    __syncthreads();
    if (tid < 128) {
        float4 a = snum[tid], bb = snum[tid + 128];
        a.x += bb.x; a.y += bb.y; a.z += bb.z; a.w += bb.w;
        snum[tid] = a;
    }
    __syncthreads();
    if (tid < 64) {
        float4 a = snum[tid], bb = snum[tid + 64];
        a.x += bb.x; a.y += bb.y; a.z += bb.z; a.w += bb.w;
        snum[tid] = a;
    }
    __syncthreads();
    if (tid < 32) {
        float4 a = snum[tid], bb = snum[tid + 32];
        a.x += bb.x; a.y += bb.y; a.z += bb.z; a.w += bb.w;
        snum[tid] = a;   // snum[0..31] flattened = num[0..127]
    }

    // norm_new + qn_dot
    if (tid < HEAD) {
        float nn = fmaf(f_g, norm[(size_t)bh * HEAD + tid], i_g * k_s[tid]);
        if (norm_out) norm_out[(size_t)bh * HEAD + tid] = nn;
        red[tid] = q_s[tid] * nn;
    }
    __syncthreads();
    #pragma unroll
    for (int off = 64; off > 0; off >>= 1) {
        if (tid < off) red[tid] += red[tid + off];
        __syncthreads();
    }
    if (tid == 0) {
        float qn = red[0];
        s_denom = fmaxf(fabsf(qn), expf(-m_new)) + 1e-6f;
        if (max_out) max_out[bh] = m_new;
    }
    __syncthreads();

    // out_pre + GroupNorm over the 128 channels of this head
    float o = 0.f;
    if (tid < HEAD) {
        o = ((const float*)snum)[tid] / s_denom;
        red[tid]  = o;
        red2[tid] = o * o;
    }
    __syncthreads();
    #pragma unroll
    for (int off = 64; off > 0; off >>= 1) {
        if (tid < off) { red[tid] += red[tid + off]; red2[tid] += red2[tid + off]; }
        __syncthreads();
    }
    if (tid == 0) {
        float mu  = red[0] * (1.f / HEAD);
        float var = red2[0] * (1.f / HEAD) - mu * mu;
        s_mu   = mu;
        s_rstd = rsqrtf(var + 1e-5f);
    }
    __syncthreads();
    if (tid < HEAD) {
        int ch = h * HEAD + tid;
        out[(size_t)b * HIDDEN + ch] = (o - s_mu) * s_rstd * gamma[ch] + beta[ch];
    }
}

// ---------------------------------------------------------------------------
extern "C" void kernel_launch(void* const* d_in, const int* in_sizes, int n_in,
                              void* d_out, int out_size)
{
    const float* q     = (const float*)d_in[0];
    const float* k     = (const float*)d_in[1];
    const float* v     = (const float*)d_in[2];
    const float* cell  = (const float*)d_in[3];
    const float* norm  = (const float*)d_in[4];
    const float* maxs  = (const float*)d_in[5];
    const float* Wi    = (const float*)d_in[6];
    const float* bi    = (const float*)d_in[7];
    const float* Wf    = (const float*)d_in[8];
    const float* bf    = (const float*)d_in[9];
    const float* gamma = (const float*)d_in[10];
    const float* beta  = (const float*)d_in[11];

    float* out = (float*)d_out;

    const size_t OUT_N  = (size_t)BATCH * HIDDEN;                 // 524288
    const size_t CELL_N = (size_t)BATCH * HEADS * HEAD * HEAD;    // 67108864
    const size_t NORM_N = (size_t)BATCH * HEADS * HEAD;           // 524288
    const size_t MAX_N  = (size_t)BATCH * HEADS;                  // 4096

    float* cell_out = 0;
    float* norm_out = 0;
    float* max_out  = 0;
    if ((size_t)out_size >= OUT_N + CELL_N + NORM_N + MAX_N) {
        cell_out = out + OUT_N;
        norm_out = cell_out + CELL_N;
        max_out  = norm_out + NORM_N;
    }

    gates_kernel<<<BATCH, 256>>>(q, k, v, Wi, bi, Wf, bf);
    mlstm_kernel<<<BATCH * HEADS, 256>>>(q, k, v, cell, norm, maxs,
                                         gamma, beta,
                                         out, cell_out, norm_out, max_out);
}

// round 2
// speedup vs baseline: 1.1575x; 1.1575x over previous
#include <cuda_runtime.h>
#include <math.h>

#define HIDDEN 1024
#define HEADS  8
#define HEAD   128
#define BATCH  512

// Scratch for gate pre-activations (allocation-free rule: __device__ globals)
__device__ float g_ig[BATCH * HEADS];
__device__ float g_fg[BATCH * HEADS];

__device__ __forceinline__ float dot4(float4 a, float4 b) {
    return a.x*b.x + a.y*b.y + a.z*b.z + a.w*b.w;
}

// ---------------------------------------------------------------------------
// Kernel 1: gate pre-activations. C[512,16] = concat(q,k,v) @ [Wi|Wf]^T + b
// 128 blocks x 256 threads; each block handles 4 batch rows, staged in smem,
// so the 192KB weight matrix is read once per block (4x less L2 traffic).
// ---------------------------------------------------------------------------
__global__ __launch_bounds__(256) void gates_kernel(
    const float* __restrict__ q, const float* __restrict__ k,
    const float* __restrict__ v,
    const float* __restrict__ Wi, const float* __restrict__ bi,
    const float* __restrict__ Wf, const float* __restrict__ bf)
{
    int tid = threadIdx.x;
    int b0  = blockIdx.x * 4;

    // 4 rows x 768 float4 = 48KB; aliased as reduction buffer afterwards
    __shared__ float4 xs[4 * 768];

    #pragma unroll
    for (int rb = 0; rb < 4; ++rb) {
        const float4* q4 = (const float4*)(q + (size_t)(b0 + rb) * HIDDEN);
        const float4* k4 = (const float4*)(k + (size_t)(b0 + rb) * HIDDEN);
        const float4* v4 = (const float4*)(v + (size_t)(b0 + rb) * HIDDEN);
        xs[rb * 768 + tid]       = q4[tid];
        xs[rb * 768 + 256 + tid] = k4[tid];
        xs[rb * 768 + 512 + tid] = v4[tid];
    }
    __syncthreads();

    const float4* Wi4 = (const float4*)Wi;   // [8][768] float4
    const float4* Wf4 = (const float4*)Wf;

    // acc[g*32 + h*4 + rb], g=0 -> igate, g=1 -> fgate
    float acc[64];
    #pragma unroll
    for (int i = 0; i < 64; ++i) acc[i] = 0.f;

    #pragma unroll
    for (int it = 0; it < 3; ++it) {
        int e4 = tid + it * 256;
        float4 x0 = xs[0 * 768 + e4];
        float4 x1 = xs[1 * 768 + e4];
        float4 x2 = xs[2 * 768 + e4];
        float4 x3 = xs[3 * 768 + e4];
        #pragma unroll
        for (int h = 0; h < 8; ++h) {
            float4 wi = Wi4[h * 768 + e4];
            acc[h*4 + 0] += dot4(wi, x0);
            acc[h*4 + 1] += dot4(wi, x1);
            acc[h*4 + 2] += dot4(wi, x2);
            acc[h*4 + 3] += dot4(wi, x3);
            float4 wf = Wf4[h * 768 + e4];
            acc[32 + h*4 + 0] += dot4(wf, x0);
            acc[32 + h*4 + 1] += dot4(wf, x1);
            acc[32 + h*4 + 2] += dot4(wf, x2);
            acc[32 + h*4 + 3] += dot4(wf, x3);
        }
    }

    // warp-level reduce all 64 accumulators
    #pragma unroll
    for (int i = 0; i < 64; ++i) {
        #pragma unroll
        for (int off = 16; off > 0; off >>= 1)
            acc[i] += __shfl_down_sync(0xffffffffu, acc[i], off);
    }

    __syncthreads();                         // xs no longer needed
    float* sred = (float*)xs;                // [8 warps][64 vals]
    int warp = tid >> 5, lane = tid & 31;
    if (lane == 0) {
        #pragma unroll
        for (int i = 0; i < 64; ++i) sred[warp * 64 + i] = acc[i];
    }
    __syncthreads();
    if (tid < 64) {
        float s = 0.f;
        #pragma unroll
        for (int w = 0; w < 8; ++w) s += sred[w * 64 + tid];
        int g  = tid >> 5;
        int h  = (tid >> 2) & 7;
        int rb = tid & 3;
        if (g == 0) g_ig[(b0 + rb) * 8 + h] = s + bi[h];
        else        g_fg[(b0 + rb) * 8 + h] = s + bf[h];
    }
}

// ---------------------------------------------------------------------------
// Kernel 2: fully fused mLSTM step + GroupNorm.
// One block per (b,h). 256 threads stream the 128x128 cell tile once.
// 8-deep explicit load batching for MLP; streaming ld/st hints (.cs).
// ---------------------------------------------------------------------------
__global__ __launch_bounds__(256) void mlstm_kernel(
    const float* __restrict__ q, const float* __restrict__ k,
    const float* __restrict__ v, const float* __restrict__ cell,
    const float* __restrict__ norm, const float* __restrict__ maxs,
    const float* __restrict__ gamma, const float* __restrict__ beta,
    float* __restrict__ out, float* __restrict__ cell_out,
    float* __restrict__ norm_out, float* __restrict__ max_out)
{
    int bh  = blockIdx.x;
    int b   = bh >> 3;
    int h   = bh & 7;
    int tid = threadIdx.x;

    __shared__ __align__(16) float q_s[HEAD];
    __shared__ __align__(16) float k_s[HEAD];
    __shared__ __align__(16) float v_s[HEAD];
    __shared__ float4 snum[256];
    __shared__ float  red[HEAD];
    __shared__ float  red2[HEAD];
    __shared__ float  s_denom, s_mu, s_rstd;

    const float rsqrtD = 0.08838834764831845f;  // 1/sqrt(128)
    if (tid < HEAD) {
        q_s[tid] = q[(size_t)b * HIDDEN + h * HEAD + tid];
        k_s[tid] = k[(size_t)b * HIDDEN + h * HEAD + tid] * rsqrtD;
        v_s[tid] = v[(size_t)b * HIDDEN + h * HEAD + tid];
    }

    // gate scalars (uniform per block)
    float igp   = g_ig[bh];
    float fgp   = g_fg[bh];
    float log_f = fminf(fgp, 0.f) - log1pf(expf(-fabsf(fgp)));   // log sigmoid
    float m_old = maxs[bh];
    float m_new = fmaxf(igp, m_old + log_f);
    float i_g   = expf(igp - m_new);
    float f_g   = expf(log_f + m_old - m_new);
    __syncthreads();

    // cell tile: warp = r0 (row-group), lane = c4 (float4 column group)
    int c4 = tid & 31;
    int r0 = tid >> 5;
    const float4* cp = (const float4*)(cell + (size_t)bh * HEAD * HEAD)
                       + r0 * 32 + c4;
    float4* op = cell_out
               ? (float4*)(cell_out + (size_t)bh * HEAD * HEAD) + r0 * 32 + c4
               : (float4*)0;

    float4 vreg = ((const float4*)v_s)[c4];
    float4 num  = make_float4(0.f, 0.f, 0.f, 0.f);

    #pragma unroll
    for (int half = 0; half < 2; ++half) {
        float4 cv[8];
        #pragma unroll
        for (int i = 0; i < 8; ++i)
            cv[i] = __ldcs(cp + (half * 8 + i) * 256);   // 8 rows ahead in flight
        #pragma unroll
        for (int i = 0; i < 8; ++i) {
            int r = (half * 8 + i) * 8 + r0;
            float a = i_g * k_s[r];
            float4 cn;
            cn.x = fmaf(f_g, cv[i].x, a * vreg.x);
            cn.y = fmaf(f_g, cv[i].y, a * vreg.y);
            cn.z = fmaf(f_g, cv[i].z, a * vreg.z);
            cn.w = fmaf(f_g, cv[i].w, a * vreg.w);
            if (op) __stcs(op + (half * 8 + i) * 256, cn);
            float qr = q_s[r];
            num.x = fmaf(qr, cn.x, num.x);
            num.y = fmaf(qr, cn.y, num.y);
            num.z = fmaf(qr, cn.z, num.z);
            num.w = fmaf(qr, cn.w, num.w);
        }
    }

    // reduce num over the 8 row-groups (same c4 every 32 threads)
    snum[tid] = num;
    __syncthreads();
    if (tid < 128) {
        float4 a = snum[tid], bb = snum[tid + 128];
        a.x += bb.x; a.y += bb.y; a.z += bb.z; a.w += bb.w;
        snum[tid] = a;
    }
    __syncthreads();
    if (tid < 64) {
        float4 a = snum[tid], bb = snum[tid + 64];
        a.x += bb.x; a.y += bb.y; a.z += bb.z; a.w += bb.w;
        snum[tid] = a;
    }
    __syncthreads();
    if (tid < 32) {
        float4 a = snum[tid], bb = snum[tid + 32];
        a.x += bb.x; a.y += bb.y; a.z += bb.z; a.w += bb.w;
        snum[tid] = a;   // snum[0..31] flattened = num[0..127]
    }

    // norm_new + qn_dot
    if (tid < HEAD) {
        float nn = fmaf(f_g, norm[(size_t)bh * HEAD + tid], i_g * k_s[tid]);
        if (norm_out) norm_out[(size_t)bh * HEAD + tid] = nn;
        red[tid] = q_s[tid] * nn;
    }
    __syncthreads();
    #pragma unroll
    for (int off = 64; off > 0; off >>= 1) {
        if (tid < off) red[tid] += red[tid + off];
        __syncthreads();
    }
    if (tid == 0) {
        float qn = red[0];
        s_denom = fmaxf(fabsf(qn), expf(-m_new)) + 1e-6f;
        if (max_out) max_out[bh] = m_new;
    }
    __syncthreads();

    // out_pre + GroupNorm over the 128 channels of this head
    float o = 0.f;
    if (tid < HEAD) {
        o = ((const float*)snum)[tid] / s_denom;
        red[tid]  = o;
        red2[tid] = o * o;
    }
    __syncthreads();
    #pragma unroll
    for (int off = 64; off > 0; off >>= 1) {
        if (tid < off) { red[tid] += red[tid + off]; red2[tid] += red2[tid + off]; }
        __syncthreads();
    }
    if (tid == 0) {
        float mu  = red[0] * (1.f / HEAD);
        float var = red2[0] * (1.f / HEAD) - mu * mu;
        s_mu   = mu;
        s_rstd = rsqrtf(var + 1e-5f);
    }
    __syncthreads();
    if (tid < HEAD) {
        int ch = h * HEAD + tid;
        out[(size_t)b * HIDDEN + ch] = (o - s_mu) * s_rstd * gamma[ch] + beta[ch];
    }
}

// ---------------------------------------------------------------------------
extern "C" void kernel_launch(void* const* d_in, const int* in_sizes, int n_in,
                              void* d_out, int out_size)
{
    const float* q     = (const float*)d_in[0];
    const float* k     = (const float*)d_in[1];
    const float* v     = (const float*)d_in[2];
    const float* cell  = (const float*)d_in[3];
    const float* norm  = (const float*)d_in[4];
    const float* maxs  = (const float*)d_in[5];
    const float* Wi    = (const float*)d_in[6];
    const float* bi    = (const float*)d_in[7];
    const float* Wf    = (const float*)d_in[8];
    const float* bf    = (const float*)d_in[9];
    const float* gamma = (const float*)d_in[10];
    const float* beta  = (const float*)d_in[11];

    float* out = (float*)d_out;

    const size_t OUT_N  = (size_t)BATCH * HIDDEN;                 // 524288
    const size_t CELL_N = (size_t)BATCH * HEADS * HEAD * HEAD;    // 67108864
    const size_t NORM_N = (size_t)BATCH * HEADS * HEAD;           // 524288
    const size_t MAX_N  = (size_t)BATCH * HEADS;                  // 4096

    float* cell_out = 0;
    float* norm_out = 0;
    float* max_out  = 0;
    if ((size_t)out_size >= OUT_N + CELL_N + NORM_N + MAX_N) {
        cell_out = out + OUT_N;
        norm_out = cell_out + CELL_N;
        max_out  = norm_out + NORM_N;
    }

    gates_kernel<<<BATCH / 4, 256>>>(q, k, v, Wi, bi, Wf, bf);
    mlstm_kernel<<<BATCH * HEADS, 256>>>(q, k, v, cell, norm, maxs,
                                         gamma, beta,
                                         out, cell_out, norm_out, max_out);
}

// round 3
// speedup vs baseline: 1.2246x; 1.0579x over previous
#include <cuda_runtime.h>
#include <math.h>

#define HIDDEN 1024
#define HEADS  8
#define HEAD   128
#define BATCH  512

__device__ __forceinline__ float dot4(float4 a, float4 b) {
    return a.x*b.x + a.y*b.y + a.z*b.z + a.w*b.w;
}

// ---------------------------------------------------------------------------
// Single fully fused kernel: gate GEMV + mLSTM step + GroupNorm.
// One block per (b,h), 256 threads.
//   1. gate pre-activations via per-thread dot4 + shuffle/smem reduce
//      (weights L2-resident; qkv rows reused 8x across heads -> L2 hits)
//   2. norm update + qn partials (shuffle-reduced, folded into later sync)
//   3. stream 128x128 cell tile once (8-deep load batches, .cs hints),
//      accumulate numerator in registers
//   4. num reduce + denominator + GroupNorm epilogue (4 syncthreads total)
// ---------------------------------------------------------------------------
__global__ __launch_bounds__(256) void mlstm_fused_kernel(
    const float* __restrict__ q, const float* __restrict__ k,
    const float* __restrict__ v, const float* __restrict__ cell,
    const float* __restrict__ norm, const float* __restrict__ maxs,
    const float* __restrict__ Wi, const float* __restrict__ bi,
    const float* __restrict__ Wf, const float* __restrict__ bf,
    const float* __restrict__ gamma, const float* __restrict__ beta,
    float* __restrict__ out, float* __restrict__ cell_out,
    float* __restrict__ norm_out, float* __restrict__ max_out)
{
    int bh   = blockIdx.x;
    int b    = bh >> 3;
    int h    = bh & 7;
    int tid  = threadIdx.x;
    int lane = tid & 31;
    int warp = tid >> 5;

    __shared__ __align__(16) float q_s[HEAD];
    __shared__ __align__(16) float k_s[HEAD];
    __shared__ __align__(16) float v_s[HEAD];
    __shared__ float4 snum[256];
    __shared__ float pig[8], pfg[8], pq[4], pm[4], pv[4];

    const float rsqrtD = 0.08838834764831845f;  // 1/sqrt(128)

    // ---- gate pre-activations: igp/fgp = qkv_row . W[h] + b[h] -------------
    const float4* qrow = (const float4*)(q + (size_t)b * HIDDEN);
    const float4* krow = (const float4*)(k + (size_t)b * HIDDEN);
    const float4* vrow = (const float4*)(v + (size_t)b * HIDDEN);
    const float4* Wi4  = (const float4*)Wi + (size_t)h * 768;
    const float4* Wf4  = (const float4*)Wf + (size_t)h * 768;

    float4 xq = qrow[tid];
    float4 xk = krow[tid];
    float4 xv = vrow[tid];

    float ai = dot4(xq, Wi4[tid]) + dot4(xk, Wi4[256 + tid]) + dot4(xv, Wi4[512 + tid]);
    float af = dot4(xq, Wf4[tid]) + dot4(xk, Wf4[256 + tid]) + dot4(xv, Wf4[512 + tid]);

    // warp h already holds the head slice in registers -> stash to smem
    if (warp == h) {
        ((float4*)q_s)[lane] = xq;
        float4 sk;
        sk.x = xk.x * rsqrtD; sk.y = xk.y * rsqrtD;
        sk.z = xk.z * rsqrtD; sk.w = xk.w * rsqrtD;
        ((float4*)k_s)[lane] = sk;
        ((float4*)v_s)[lane] = xv;
    }

    #pragma unroll
    for (int off = 16; off > 0; off >>= 1) {
        ai += __shfl_xor_sync(0xffffffffu, ai, off);
        af += __shfl_xor_sync(0xffffffffu, af, off);
    }
    if (lane == 0) { pig[warp] = ai; pfg[warp] = af; }
    __syncthreads();                                   // sync #1

    float igp = bi[h], fgp = bf[h];
    #pragma unroll
    for (int w = 0; w < 8; ++w) { igp += pig[w]; fgp += pfg[w]; }

    float log_f = fminf(fgp, 0.f) - log1pf(expf(-fabsf(fgp)));   // log sigmoid
    float m_old = maxs[bh];
    float m_new = fmaxf(igp, m_old + log_f);
    float i_g   = expf(igp - m_new);
    float f_g   = expf(log_f + m_old - m_new);

    if (tid == 0 && max_out) max_out[bh] = m_new;

    // ---- norm update + qn partials (reduction deferred to sync #2) ---------
    if (tid < HEAD) {
        float nn = fmaf(f_g, norm[(size_t)bh * HEAD + tid], i_g * k_s[tid]);
        if (norm_out) norm_out[(size_t)bh * HEAD + tid] = nn;
        float qn = q_s[tid] * nn;
        #pragma unroll
        for (int off = 16; off > 0; off >>= 1)
            qn += __shfl_xor_sync(0xffffffffu, qn, off);
        if (lane == 0) pq[warp] = qn;
    }

    // ---- stream the cell tile: warp = row-group, lane = float4 column ------
    int c4 = lane;
    int r0 = warp;
    const float4* cp = (const float4*)(cell + (size_t)bh * HEAD * HEAD)
                       + r0 * 32 + c4;
    float4* op = cell_out
               ? (float4*)(cell_out + (size_t)bh * HEAD * HEAD) + r0 * 32 + c4
               : (float4*)0;

    float4 vreg = ((const float4*)v_s)[c4];
    float4 num  = make_float4(0.f, 0.f, 0.f, 0.f);

    #pragma unroll
    for (int half = 0; half < 2; ++half) {
        float4 cv[8];
        #pragma unroll
        for (int i = 0; i < 8; ++i)
            cv[i] = __ldcs(cp + (half * 8 + i) * 256);   // 8 rows in flight
        #pragma unroll
        for (int i = 0; i < 8; ++i) {
            int r = (half * 8 + i) * 8 + r0;
            float a = i_g * k_s[r];
            float4 cn;
            cn.x = fmaf(f_g, cv[i].x, a * vreg.x);
            cn.y = fmaf(f_g, cv[i].y, a * vreg.y);
            cn.z = fmaf(f_g, cv[i].z, a * vreg.z);
            cn.w = fmaf(f_g, cv[i].w, a * vreg.w);
            if (op) __stcs(op + (half * 8 + i) * 256, cn);
            float qr = q_s[r];
            num.x = fmaf(qr, cn.x, num.x);
            num.y = fmaf(qr, cn.y, num.y);
            num.z = fmaf(qr, cn.z, num.z);
            num.w = fmaf(qr, cn.w, num.w);
        }
    }

    // ---- numerator reduction over the 8 row-groups --------------------------
    snum[tid] = num;
    __syncthreads();                                   // sync #2 (covers pq)
    if (tid < 32) {
        float4 a = snum[tid];
        #pragma unroll
        for (int j = 1; j < 8; ++j) {
            float4 bb = snum[tid + 32 * j];
            a.x += bb.x; a.y += bb.y; a.z += bb.z; a.w += bb.w;
        }
        snum[tid] = a;   // flattened: num[0..127]
    }
    __syncthreads();                                   // sync #3

    // ---- denominator + out_pre + GN stats -----------------------------------
    float o = 0.f, so = 0.f, so2 = 0.f;
    if (tid < HEAD) {
        float qn    = pq[0] + pq[1] + pq[2] + pq[3];
        float denom = fmaxf(fabsf(qn), expf(-m_new)) + 1e-6f;
        o   = ((const float*)snum)[tid] / denom;
        so  = o;
        so2 = o * o;
    }
    #pragma unroll
    for (int off = 16; off > 0; off >>= 1) {
        so  += __shfl_xor_sync(0xffffffffu, so,  off);
        so2 += __shfl_xor_sync(0xffffffffu, so2, off);
    }
    if (tid < HEAD && lane == 0) { pm[warp] = so; pv[warp] = so2; }
    __syncthreads();                                   // sync #4

    if (tid < HEAD) {
        float mu   = (pm[0] + pm[1] + pm[2] + pm[3]) * (1.f / HEAD);
        float var  = (pv[0] + pv[1] + pv[2] + pv[3]) * (1.f / HEAD) - mu * mu;
        float rstd = rsqrtf(var + 1e-5f);
        int ch = h * HEAD + tid;
        out[(size_t)b * HIDDEN + ch] = (o - mu) * rstd * gamma[ch] + beta[ch];
    }
}

// ---------------------------------------------------------------------------
extern "C" void kernel_launch(void* const* d_in, const int* in_sizes, int n_in,
                              void* d_out, int out_size)
{
    const float* q     = (const float*)d_in[0];
    const float* k     = (const float*)d_in[1];
    const float* v     = (const float*)d_in[2];
    const float* cell  = (const float*)d_in[3];
    const float* norm  = (const float*)d_in[4];
    const float* maxs  = (const float*)d_in[5];
    const float* Wi    = (const float*)d_in[6];
    const float* bi    = (const float*)d_in[7];
    const float* Wf    = (const float*)d_in[8];
    const float* bf    = (const float*)d_in[9];
    const float* gamma = (const float*)d_in[10];
    const float* beta  = (const float*)d_in[11];

    float* out = (float*)d_out;

    const size_t OUT_N  = (size_t)BATCH * HIDDEN;                 // 524288
    const size_t CELL_N = (size_t)BATCH * HEADS * HEAD * HEAD;    // 67108864
    const size_t NORM_N = (size_t)BATCH * HEADS * HEAD;           // 524288
    const size_t MAX_N  = (size_t)BATCH * HEADS;                  // 4096

    float* cell_out = 0;
    float* norm_out = 0;
    float* max_out  = 0;
    if ((size_t)out_size >= OUT_N + CELL_N + NORM_N + MAX_N) {
        cell_out = out + OUT_N;
        norm_out = cell_out + CELL_N;
        max_out  = norm_out + NORM_N;
    }

    mlstm_fused_kernel<<<BATCH * HEADS, 256>>>(q, k, v, cell, norm, maxs,
                                               Wi, bi, Wf, bf, gamma, beta,
                                               out, cell_out, norm_out, max_out);
}

// round 4
// speedup vs baseline: 1.2375x; 1.0106x over previous
#include <cuda_runtime.h>
#include <math.h>

#define HIDDEN 1024
#define HEADS  8
#define HEAD   128
#define BATCH  512

__device__ __forceinline__ float dot4(float4 a, float4 b) {
    return a.x*b.x + a.y*b.y + a.z*b.z + a.w*b.w;
}

// ---------------------------------------------------------------------------
// Single fully fused kernel: gate GEMV + mLSTM step + GroupNorm.
// One block per (b,h), 256 threads.
// Key memory-pipeline structure:
//   - first 8 cell-row loads issued at kernel ENTRY (independent of gates),
//     so the gate GEMV + reductions hide entirely under cell-load latency
//   - main loop is a rolling depth-8 software pipeline: consume one row,
//     immediately issue the load 8 rows ahead -> constant MLP=8 per warp
// ---------------------------------------------------------------------------
__global__ __launch_bounds__(256) void mlstm_fused_kernel(
    const float* __restrict__ q, const float* __restrict__ k,
    const float* __restrict__ v, const float* __restrict__ cell,
    const float* __restrict__ norm, const float* __restrict__ maxs,
    const float* __restrict__ Wi, const float* __restrict__ bi,
    const float* __restrict__ Wf, const float* __restrict__ bf,
    const float* __restrict__ gamma, const float* __restrict__ beta,
    float* __restrict__ out, float* __restrict__ cell_out,
    float* __restrict__ norm_out, float* __restrict__ max_out)
{
    int bh   = blockIdx.x;
    int b    = bh >> 3;
    int h    = bh & 7;
    int tid  = threadIdx.x;
    int lane = tid & 31;
    int warp = tid >> 5;

    __shared__ __align__(16) float q_s[HEAD];
    __shared__ __align__(16) float k_s[HEAD];
    __shared__ __align__(16) float v_s[HEAD];
    __shared__ float4 snum[256];
    __shared__ float pig[8], pfg[8], pq[4], pm[4], pv[4];

    const float rsqrtD = 0.08838834764831845f;  // 1/sqrt(128)

    // ---- cell tile pointers: warp = row-group, lane = float4 column --------
    const float4* cp = (const float4*)(cell + (size_t)bh * HEAD * HEAD)
                       + warp * 32 + lane;
    float4* op = cell_out
               ? (float4*)(cell_out + (size_t)bh * HEAD * HEAD) + warp * 32 + lane
               : (float4*)0;

    // ---- prefetch first 8 cell rows BEFORE the gate GEMV -------------------
    float4 cv[8];
    #pragma unroll
    for (int i = 0; i < 8; ++i)
        cv[i] = __ldcs(cp + i * 256);

    // ---- gate pre-activations: igp/fgp = qkv_row . W[h] + b[h] -------------
    const float4* qrow = (const float4*)(q + (size_t)b * HIDDEN);
    const float4* krow = (const float4*)(k + (size_t)b * HIDDEN);
    const float4* vrow = (const float4*)(v + (size_t)b * HIDDEN);
    const float4* Wi4  = (const float4*)Wi + (size_t)h * 768;
    const float4* Wf4  = (const float4*)Wf + (size_t)h * 768;

    float4 xq = qrow[tid];
    float4 xk = krow[tid];
    float4 xv = vrow[tid];

    float ai = dot4(xq, Wi4[tid]) + dot4(xk, Wi4[256 + tid]) + dot4(xv, Wi4[512 + tid]);
    float af = dot4(xq, Wf4[tid]) + dot4(xk, Wf4[256 + tid]) + dot4(xv, Wf4[512 + tid]);

    // warp h already holds the head slice in registers -> stash to smem
    if (warp == h) {
        ((float4*)q_s)[lane] = xq;
        float4 sk;
        sk.x = xk.x * rsqrtD; sk.y = xk.y * rsqrtD;
        sk.z = xk.z * rsqrtD; sk.w = xk.w * rsqrtD;
        ((float4*)k_s)[lane] = sk;
        ((float4*)v_s)[lane] = xv;
    }

    #pragma unroll
    for (int off = 16; off > 0; off >>= 1) {
        ai += __shfl_xor_sync(0xffffffffu, ai, off);
        af += __shfl_xor_sync(0xffffffffu, af, off);
    }
    if (lane == 0) { pig[warp] = ai; pfg[warp] = af; }
    __syncthreads();                                   // sync #1

    float igp = bi[h], fgp = bf[h];
    #pragma unroll
    for (int w = 0; w < 8; ++w) { igp += pig[w]; fgp += pfg[w]; }

    float log_f = fminf(fgp, 0.f) - log1pf(expf(-fabsf(fgp)));   // log sigmoid
    float m_old = maxs[bh];
    float m_new = fmaxf(igp, m_old + log_f);
    float i_g   = expf(igp - m_new);
    float f_g   = expf(log_f + m_old - m_new);

    if (tid == 0 && max_out) max_out[bh] = m_new;

    // ---- norm update + qn partials (reduction deferred to sync #2) ---------
    if (tid < HEAD) {
        float nn = fmaf(f_g, norm[(size_t)bh * HEAD + tid], i_g * k_s[tid]);
        if (norm_out) norm_out[(size_t)bh * HEAD + tid] = nn;
        float qn = q_s[tid] * nn;
        #pragma unroll
        for (int off = 16; off > 0; off >>= 1)
            qn += __shfl_xor_sync(0xffffffffu, qn, off);
        if (lane == 0) pq[warp] = qn;
    }

    // ---- main stream: rolling depth-8 pipeline over 16 rows -----------------
    float4 vreg = ((const float4*)v_s)[lane];
    float4 num  = make_float4(0.f, 0.f, 0.f, 0.f);

    #pragma unroll
    for (int i = 0; i < 16; ++i) {
        float4 c = cv[i & 7];
        if (i + 8 < 16)
            cv[i & 7] = __ldcs(cp + (i + 8) * 256);   // keep 8 rows in flight
        int r = i * 8 + warp;
        float a = i_g * k_s[r];
        float4 cn;
        cn.x = fmaf(f_g, c.x, a * vreg.x);
        cn.y = fmaf(f_g, c.y, a * vreg.y);
        cn.z = fmaf(f_g, c.z, a * vreg.z);
        cn.w = fmaf(f_g, c.w, a * vreg.w);
        if (op) __stcs(op + i * 256, cn);
        float qr = q_s[r];
        num.x = fmaf(qr, cn.x, num.x);
        num.y = fmaf(qr, cn.y, num.y);
        num.z = fmaf(qr, cn.z, num.z);
        num.w = fmaf(qr, cn.w, num.w);
    }

    // ---- numerator reduction over the 8 row-groups --------------------------
    snum[tid] = num;
    __syncthreads();                                   // sync #2 (covers pq)
    if (tid < 32) {
        float4 a = snum[tid];
        #pragma unroll
        for (int j = 1; j < 8; ++j) {
            float4 bb = snum[tid + 32 * j];
            a.x += bb.x; a.y += bb.y; a.z += bb.z; a.w += bb.w;
        }
        snum[tid] = a;   // flattened: num[0..127]
    }
    __syncthreads();                                   // sync #3

    // ---- denominator + out_pre + GN stats -----------------------------------
    float o = 0.f, so = 0.f, so2 = 0.f;
    if (tid < HEAD) {
        float qn    = pq[0] + pq[1] + pq[2] + pq[3];
        float denom = fmaxf(fabsf(qn), expf(-m_new)) + 1e-6f;
        o   = ((const float*)snum)[tid] / denom;
        so  = o;
        so2 = o * o;
    }
    #pragma unroll
    for (int off = 16; off > 0; off >>= 1) {
        so  += __shfl_xor_sync(0xffffffffu, so,  off);
        so2 += __shfl_xor_sync(0xffffffffu, so2, off);
    }
    if (tid < HEAD && lane == 0) { pm[warp] = so; pv[warp] = so2; }
    __syncthreads();                                   // sync #4

    if (tid < HEAD) {
        float mu   = (pm[0] + pm[1] + pm[2] + pm[3]) * (1.f / HEAD);
        float var  = (pv[0] + pv[1] + pv[2] + pv[3]) * (1.f / HEAD) - mu * mu;
        float rstd = rsqrtf(var + 1e-5f);
        int ch = h * HEAD + tid;
        out[(size_t)b * HIDDEN + ch] = (o - mu) * rstd * gamma[ch] + beta[ch];
    }
}

// ---------------------------------------------------------------------------
extern "C" void kernel_launch(void* const* d_in, const int* in_sizes, int n_in,
                              void* d_out, int out_size)
{
    const float* q     = (const float*)d_in[0];
    const float* k     = (const float*)d_in[1];
    const float* v     = (const float*)d_in[2];
    const float* cell  = (const float*)d_in[3];
    const float* norm  = (const float*)d_in[4];
    const float* maxs  = (const float*)d_in[5];
    const float* Wi    = (const float*)d_in[6];
    const float* bi    = (const float*)d_in[7];
    const float* Wf    = (const float*)d_in[8];
    const float* bf    = (const float*)d_in[9];
    const float* gamma = (const float*)d_in[10];
    const float* beta  = (const float*)d_in[11];

    float* out = (float*)d_out;

    const size_t OUT_N  = (size_t)BATCH * HIDDEN;                 // 524288
    const size_t CELL_N = (size_t)BATCH * HEADS * HEAD * HEAD;    // 67108864
    const size_t NORM_N = (size_t)BATCH * HEADS * HEAD;           // 524288
    const size_t MAX_N  = (size_t)BATCH * HEADS;                  // 4096

    float* cell_out = 0;
    float* norm_out = 0;
    float* max_out  = 0;
    if ((size_t)out_size >= OUT_N + CELL_N + NORM_N + MAX_N) {
        cell_out = out + OUT_N;
        norm_out = cell_out + CELL_N;
        max_out  = norm_out + NORM_N;
    }

    mlstm_fused_kernel<<<BATCH * HEADS, 256>>>(q, k, v, cell, norm, maxs,
                                               Wi, bi, Wf, bf, gamma, beta,
                                               out, cell_out, norm_out, max_out);
}